// round 7
// baseline (speedup 1.0000x reference)
#include <cuda_runtime.h>

#define N_ 4
#define C_ 128
#define T_ 512
#define V_ 25
#define H_ 16
#define O_ 128
#define EPS_ 1e-5f
#define YCNT 51200.0f   // N*T*V

typedef unsigned long long ull;

// ---------------- scratch ----------------------------------------------------
__device__ float g_q[N_ * T_ * H_];          // [n][t][h]
__device__ float g_k[N_ * T_ * H_];          // [n][t][h]
__device__ float g_wvt[C_ * O_];             // [c][o]
__device__ float g_v[N_ * T_ * O_ * 32];     // [n][t][o][32] (25 data + zeros)
__device__ float g_vsum[N_ * O_ * 32];       // [n][o][32]
__device__ float g_y[(size_t)N_ * O_ * T_ * 26]; // [n][o][g][26]
__device__ float g_chsum[O_];
__device__ float g_chsq[O_];

// ---------------- helpers -----------------------------------------------------
__device__ __forceinline__ ull ffma2(ull a, ull b, ull c) {
    ull d; asm("fma.rn.f32x2 %0, %1, %2, %3;" : "=l"(d) : "l"(a), "l"(b), "l"(c)); return d;
}
__device__ __forceinline__ ull fmul2(ull a, ull b) {
    ull d; asm("mul.rn.f32x2 %0, %1, %2;" : "=l"(d) : "l"(a), "l"(b)); return d;
}
__device__ __forceinline__ ull fadd2(ull a, ull b) {
    ull d; asm("add.rn.f32x2 %0, %1, %2;" : "=l"(d) : "l"(a), "l"(b)); return d;
}
__device__ __forceinline__ ull dup2(float x) {
    ull d; asm("mov.b64 %0, {%1, %1};" : "=l"(d) : "f"(x)); return d;
}
__device__ __forceinline__ ull pack2(float x, float y) {
    ull d; asm("mov.b64 %0, {%1, %2};" : "=l"(d) : "f"(x), "f"(y)); return d;
}
__device__ __forceinline__ float2 unpack2(ull a) {
    float2 r; asm("mov.b64 {%0, %1}, %2;" : "=f"(r.x), "=f"(r.y) : "l"(a)); return r;
}
__device__ __forceinline__ float tanh_fast(float x) {
    float r; asm("tanh.approx.f32 %0, %1;" : "=f"(r) : "f"(x)); return r;
}

// ---------------- K1: q,k + housekeeping --------------------------------------
__global__ void qk_kernel(const float* __restrict__ x,
                          const float* __restrict__ Wq, const float* __restrict__ bq,
                          const float* __restrict__ Wk, const float* __restrict__ bk,
                          const float* __restrict__ Wv) {
    __shared__ float xm[C_];
    int b = blockIdx.x; int n = b >> 9; int t = b & 511;
    int tid = threadIdx.x;
    int c = tid;

    if (b < 128) {
        g_vsum[b * 128 + tid] = 0.f;
    } else if (b == 128) {
        g_chsum[tid] = 0.f; g_chsq[tid] = 0.f;
    } else if (b >= 256 && b < 384) {
        int i = (b - 256) * 128 + tid;
        int o = i >> 7, cc = i & 127;
        g_wvt[cc * O_ + o] = Wv[i];
    }

    const float* xp = x + ((n * C_ + c) * T_ + t) * V_;
    float s = 0.f;
#pragma unroll
    for (int v = 0; v < V_; v++) s += xp[v];
    xm[c] = s * (1.0f / 25.0f);
    __syncthreads();
    if (tid < 32) {
        int h = tid & 15;
        bool isQ = tid < 16;
        const float* W = isQ ? Wq : Wk;
        float acc = isQ ? bq[h] : bk[h];
#pragma unroll 8
        for (int cc = 0; cc < C_; cc++) acc += W[h * C_ + cc] * xm[cc];
        float* dst = isQ ? g_q : g_k;
        dst[(n * T_ + t) * H_ + h] = acc;
    }
}

// ---------------- K2: v projection --------------------------------------------
__global__ void v_kernel(const float* __restrict__ x, const float* __restrict__ bv) {
    __shared__ float xs[C_][28];
    int b = blockIdx.x; int n = b >> 9; int t = b & 511;
    int o = threadIdx.x;
    {
        const float* xp = x + ((n * C_ + o) * T_ + t) * V_;
#pragma unroll
        for (int v = 0; v < V_; v++) xs[o][v] = xp[v];
        xs[o][25] = 0.f; xs[o][26] = 0.f; xs[o][27] = 0.f;
    }
    __syncthreads();
    ull acc[13];
    ull binit = dup2(bv[o]);
#pragma unroll
    for (int j = 0; j < 13; j++) acc[j] = binit;
    for (int c = 0; c < C_; c++) {
        ull wd = dup2(g_wvt[c * O_ + o]);
        const ulonglong2* xr = (const ulonglong2*)xs[c];
#pragma unroll
        for (int j = 0; j < 6; j++) {
            ulonglong2 p = xr[j];
            acc[2 * j]     = ffma2(wd, p.x, acc[2 * j]);
            acc[2 * j + 1] = ffma2(wd, p.y, acc[2 * j + 1]);
        }
        acc[12] = ffma2(wd, *((const ull*)xs[c] + 12), acc[12]);
    }
    float* row = g_v + (((size_t)(n * T_ + t)) * O_ + o) * 32;
#pragma unroll
    for (int j = 0; j < 12; j++) {
        float2 u = unpack2(acc[j]);
        row[2 * j] = u.x; row[2 * j + 1] = u.y;
    }
    { float2 u = unpack2(acc[12]); row[24] = u.x; }
#pragma unroll
    for (int p = 25; p < 32; p++) row[p] = 0.f;
}

// ---------------- K3: vsum ------------------------------------------------------
__global__ void vsum_kernel() {
    __shared__ float red[8][33];
    int bx = blockIdx.x;
    int n = bx >> 8, o = (bx >> 1) & 127, half = bx & 1;
    int tid = threadIdx.x;
    int tsub = tid >> 5, comp = tid & 31;
    int t0 = half * 256 + tsub * 32;
    const float* base = g_v + (((size_t)(n * T_ + t0)) * O_ + o) * 32 + comp;
    float a0 = 0.f, a1 = 0.f, a2 = 0.f, a3 = 0.f;
#pragma unroll
    for (int u = 0; u < 32; u += 4) {
        a0 += base[(size_t)(u + 0) * O_ * 32];
        a1 += base[(size_t)(u + 1) * O_ * 32];
        a2 += base[(size_t)(u + 2) * O_ * 32];
        a3 += base[(size_t)(u + 3) * O_ * 32];
    }
    red[tsub][comp] = (a0 + a1) + (a2 + a3);
    __syncthreads();
    if (tsub == 0) {
        float s = 0.f;
#pragma unroll
        for (int r = 0; r < 8; r++) s += red[r][comp];
        atomicAdd(&g_vsum[(n * O_ + o) * 32 + comp], s);
    }
}

// ---------------- K4: fused attention — single barrier/chunk pipeline ------------
// 256 threads, tile (n, o16, g16). grid 1024, 3 blocks/SM.
// smem (floats): k_s[8192] | S_s[2][16g][132] | A_s[2][16o][132]
#define TCH 8
#define NCHUNK (T_ / TCH)            // 64
#define ROWP 132
#define SM_SS 8192
#define SM_AS (SM_SS + 2 * 16 * ROWP)   // 12416
#define SM_TOT (SM_AS + 2 * 16 * ROWP)  // 16640 floats = 66560 B
#define SBUF (16 * ROWP)
#define ABUF (16 * ROWP)

// tanh stage: S[buf][gA][tt*16+hA] for chunk cc
__device__ __forceinline__ void a_stage(const float* __restrict__ k_s, float* __restrict__ Sb,
                                        float qv, int gA, int hA, int cc) {
    const float* kp = k_s + cc * TCH * 16 + hA;
    float* so = Sb + gA * ROWP + hA;
#pragma unroll
    for (int tt = 0; tt < TCH; tt++) so[tt * 16] = tanh_fast(qv - kp[tt * 16]);
}

// B stage: A[o][tt*16 + g0..7] = Wr[o,:] . S[g][tt][:]
__device__ __forceinline__ void b_stage(const float* __restrict__ Sb, float* __restrict__ Ab,
                                        const ull* __restrict__ w, int oB, int ttB, int ghB) {
    float outv[8];
    const float* srow = Sb + ttB * 16;
#pragma unroll
    for (int i = 0; i < 8; i++) {
        int g = ghB * 8 + i;
        const ulonglong2* sp = (const ulonglong2*)(srow + g * ROWP);
        ulonglong2 sa = sp[0], sb2 = sp[1];
        ull a0 = fmul2(w[0], sa.x);  a0 = ffma2(w[1], sa.y, a0);
        a0 = ffma2(w[2], sb2.x, a0); a0 = ffma2(w[3], sb2.y, a0);
        ulonglong2 sc = sp[2], sd = sp[3];
        ull a1 = fmul2(w[4], sc.x);  a1 = ffma2(w[5], sc.y, a1);
        a1 = ffma2(w[6], sd.x, a1);  a1 = ffma2(w[7], sd.y, a1);
        float2 u = unpack2(fadd2(a0, a1));
        outv[i] = u.x + u.y;
    }
    float4* dst = (float4*)(Ab + oB * ROWP + ttB * 16 + ghB * 8);
    dst[0] = make_float4(outv[0], outv[1], outv[2], outv[3]);
    dst[1] = make_float4(outv[4], outv[5], outv[6], outv[7]);
}

// C stage: full 16 g per tt
__device__ __forceinline__ void c_full(const float* __restrict__ Ab, int oC,
                                       const ull* __restrict__ vc,
                                       ull* __restrict__ acc0, ull* __restrict__ acc1) {
    const float* arow = Ab + oC * ROWP;
#pragma unroll
    for (int tt = 0; tt < TCH; tt++) {
        const ulonglong2* ap = (const ulonglong2*)(arow + tt * 16);
        ulonglong2 aA = ap[0], aB = ap[1], aC = ap[2], aD = ap[3];
        float2 vv = unpack2(vc[tt]);
        ull d0 = dup2(vv.x), d1 = dup2(vv.y);
        acc0[0] = ffma2(aA.x, d0, acc0[0]);
        acc0[1] = ffma2(aA.y, d0, acc0[1]);
        acc0[2] = ffma2(aB.x, d0, acc0[2]);
        acc0[3] = ffma2(aB.y, d0, acc0[3]);
        acc0[4] = ffma2(aC.x, d0, acc0[4]);
        acc0[5] = ffma2(aC.y, d0, acc0[5]);
        acc0[6] = ffma2(aD.x, d0, acc0[6]);
        acc0[7] = ffma2(aD.y, d0, acc0[7]);
        acc1[0] = ffma2(aA.x, d1, acc1[0]);
        acc1[1] = ffma2(aA.y, d1, acc1[1]);
        acc1[2] = ffma2(aB.x, d1, acc1[2]);
        acc1[3] = ffma2(aB.y, d1, acc1[3]);
        acc1[4] = ffma2(aC.x, d1, acc1[4]);
        acc1[5] = ffma2(aC.y, d1, acc1[5]);
        acc1[6] = ffma2(aD.x, d1, acc1[6]);
        acc1[7] = ffma2(aD.y, d1, acc1[7]);
    }
}

__global__ void __launch_bounds__(256, 3)
attn_kernel(const float* __restrict__ Wr, const float* __restrict__ br) {
    extern __shared__ float sm[];
    float* k_s = sm;
    float* S_s = sm + SM_SS;
    float* A_s = sm + SM_AS;

    int bx = blockIdx.x;
    int gt = bx & 31, ot = (bx >> 5) & 7, n = bx >> 8;
    int o_base = ot * 16, g_base = gt * 16;
    int tid = threadIdx.x;

    // roles
    int hA = tid & 15, gA = tid >> 4;                        // tanh stage
    int oB = tid & 15, ttB = (tid >> 4) & 7, ghB = tid >> 7; // B stage
    int oC = tid / 13, jC = tid - oC * 13;                   // C stage (tid<208)
    bool actC = tid < 208;

    // load k slice
    {
        const float4* kg = (const float4*)(g_k + n * T_ * H_);
        float4* k4 = (float4*)k_s;
#pragma unroll
        for (int i = 0; i < 8; i++) k4[tid + i * 256] = kg[tid + i * 256];
    }
    float qv = g_q[(n * T_ + g_base + gA) * H_ + hA];

    ull w[8];
    {
        const ull* wp = (const ull*)(Wr + (o_base + oB) * H_);
#pragma unroll
        for (int j = 0; j < 8; j++) w[j] = wp[j];
    }

    ull acc0[8], acc1[8];
    ull vcur[8];
    const float* vbase = g_v + (((size_t)n * T_) * O_ + o_base + oC) * 32 + 2 * jC;
    if (actC) {
        float brv = br[o_base + oC];
        const float* vs = g_vsum + (n * O_ + o_base + oC) * 32 + 2 * jC;
        ull i0 = dup2(brv * vs[0]);
        ull i1 = dup2(brv * vs[1]);
#pragma unroll
        for (int p = 0; p < 8; p++) { acc0[p] = i0; acc1[p] = i1; }
#pragma unroll
        for (int tt = 0; tt < TCH; tt++)
            vcur[tt] = *(const ull*)(vbase + (size_t)tt * O_ * 32);
    }
    __syncthreads();   // k_s visible

    // prologue: S(0) -> buf0
    a_stage(k_s, S_s, qv, gA, hA, 0);
    __syncthreads();
    // prologue: S(1) -> buf1, B(0) -> A buf0
    a_stage(k_s, S_s + SBUF, qv, gA, hA, 1);
    b_stage(S_s, A_s, w, oB, ttB, ghB);
    __syncthreads();

    // main loop: ONE barrier per chunk
    for (int c = 0; c < NCHUNK; c++) {
        int ab = c & 1;
        if (c < NCHUNK - 2)
            a_stage(k_s, S_s + ab * SBUF, qv, gA, hA, c + 2);        // S(c+2) -> buf c&1
        if (c < NCHUNK - 1)
            b_stage(S_s + (ab ^ 1) * SBUF, A_s + (ab ^ 1) * ABUF, w, oB, ttB, ghB); // A(c+1)
        if (actC) {
            c_full(A_s + ab * ABUF, oC, vcur, acc0, acc1);           // consume A(c)
            if (c < NCHUNK - 1) {
                const float* vb2 = vbase + (size_t)(c + 1) * TCH * O_ * 32;
#pragma unroll
                for (int tt = 0; tt < TCH; tt++)
                    vcur[tt] = *(const ull*)(vb2 + (size_t)tt * O_ * 32);
            }
        }
        __syncthreads();
    }

    // ---- epilogue: y writes + BN partial stats ----
    float sum = 0.f, sq = 0.f;
    if (actC) {
        int o0 = o_base + oC;
        float* ybase = g_y + (((size_t)(n * O_ + o0)) * T_ + g_base) * 26 + 2 * jC;
#pragma unroll
        for (int p = 0; p < 8; p++) {
            float2 u0 = unpack2(acc0[p]);
            float2 u1 = unpack2(acc1[p]);
            *(ull*)(ybase + (2 * p) * 26)     = pack2(u0.x, u1.x);
            *(ull*)(ybase + (2 * p + 1) * 26) = pack2(u0.y, u1.y);
            sum += u0.x + u0.y + u1.x + u1.y;
            sq  += u0.x * u0.x + u0.y * u0.y + u1.x * u1.x + u1.y * u1.y;
        }
    }
    __syncthreads();
    float* red = sm;
    if (tid < 32) red[tid] = 0.f;
    __syncthreads();
    if (actC) {
        atomicAdd(&red[oC], sum);
        atomicAdd(&red[16 + oC], sq);
    }
    __syncthreads();
    if (tid < 16)       atomicAdd(&g_chsum[o_base + tid], red[tid]);
    else if (tid < 32)  atomicAdd(&g_chsq[o_base + tid - 16], red[tid]);
}

// ---------------- K5: BN + residual + ReLU ----------------------------------------
__global__ void bn_kernel(const float* __restrict__ x,
                          const float* __restrict__ gamma, const float* __restrict__ beta,
                          float* __restrict__ out) {
    int bx = blockIdx.x;
    int n = bx >> 7, o = bx & 127;
    int tid = threadIdx.x;
    float mu  = g_chsum[o] * (1.0f / YCNT);
    float var = g_chsq[o] * (1.0f / YCNT) - mu * mu;
    float r = rsqrtf(var + EPS_);
    float gam = gamma[o] * r;
    float bet = beta[o] - mu * gam;
    const float* xb = x + (((size_t)(n * C_ + o)) * T_) * V_;
    const float* yb = g_y + ((size_t)(n * O_ + o)) * T_ * 26;
    float* ob = out + (((size_t)(n * O_ + o)) * T_) * V_;
#pragma unroll
    for (int i = 0; i < 25; i++) {
        int e = tid + i * 512;
        int t = (int)(((unsigned)e * 5243u) >> 17);
        float yv = yb[e + t];
        float val = yv * gam + bet + xb[e];
        ob[e] = fmaxf(val, 0.f);
    }
}

// ---------------- launcher ----------------------------------------------------------
extern "C" void kernel_launch(void* const* d_in, const int* in_sizes, int n_in,
                              void* d_out, int out_size) {
    const float* x     = (const float*)d_in[0];
    const float* Wq    = (const float*)d_in[1];
    const float* bq    = (const float*)d_in[2];
    const float* Wk    = (const float*)d_in[3];
    const float* bk    = (const float*)d_in[4];
    const float* Wv    = (const float*)d_in[5];
    const float* bv    = (const float*)d_in[6];
    const float* Wr    = (const float*)d_in[7];
    const float* br    = (const float*)d_in[8];
    const float* gamma = (const float*)d_in[9];
    const float* beta  = (const float*)d_in[10];
    float* out = (float*)d_out;

    const int smem_bytes = SM_TOT * 4;   // 66560
    cudaFuncSetAttribute(attn_kernel, cudaFuncAttributeMaxDynamicSharedMemorySize, smem_bytes);

    qk_kernel<<<N_ * T_, 128>>>(x, Wq, bq, Wk, bk, Wv);   // 1 (+housekeeping)
    v_kernel<<<N_ * T_, 128>>>(x, bv);                     // 2
    vsum_kernel<<<1024, 256>>>();                          // 3
    attn_kernel<<<1024, 256, smem_bytes>>>(Wr, br);        // 4  <- profiled
    bn_kernel<<<512, 512>>>(x, gamma, beta, out);          // 5
}

// round 8
// speedup vs baseline: 1.2822x; 1.2822x over previous
#include <cuda_runtime.h>

#define N_ 4
#define C_ 128
#define T_ 512
#define V_ 25
#define H_ 16
#define O_ 128
#define EPS_ 1e-5f
#define YCNT 51200.0f   // N*T*V

typedef unsigned long long ull;

// ---------------- scratch ----------------------------------------------------
__device__ float g_q[N_ * T_ * H_];          // [n][t][h]
__device__ float g_k[N_ * T_ * H_];          // [n][t][h]
__device__ float g_wvt[C_ * O_];             // [c][o]
__device__ float g_v[N_ * T_ * O_ * 32];     // [n][t][o][32] (25 data + zeros)
__device__ float g_vsum[N_ * O_ * 32];       // [n][o][32]
__device__ float g_y[(size_t)N_ * O_ * T_ * 26]; // [n][o][g][26]
__device__ float g_chsum[O_];
__device__ float g_chsq[O_];

// ---------------- helpers -----------------------------------------------------
__device__ __forceinline__ ull ffma2(ull a, ull b, ull c) {
    ull d; asm("fma.rn.f32x2 %0, %1, %2, %3;" : "=l"(d) : "l"(a), "l"(b), "l"(c)); return d;
}
__device__ __forceinline__ ull fmul2(ull a, ull b) {
    ull d; asm("mul.rn.f32x2 %0, %1, %2;" : "=l"(d) : "l"(a), "l"(b)); return d;
}
__device__ __forceinline__ ull fadd2(ull a, ull b) {
    ull d; asm("add.rn.f32x2 %0, %1, %2;" : "=l"(d) : "l"(a), "l"(b)); return d;
}
__device__ __forceinline__ ull dup2(float x) {
    ull d; asm("mov.b64 %0, {%1, %1};" : "=l"(d) : "f"(x)); return d;
}
__device__ __forceinline__ ull pack2(float x, float y) {
    ull d; asm("mov.b64 %0, {%1, %2};" : "=l"(d) : "f"(x), "f"(y)); return d;
}
__device__ __forceinline__ float2 unpack2(ull a) {
    float2 r; asm("mov.b64 {%0, %1}, %2;" : "=f"(r.x), "=f"(r.y) : "l"(a)); return r;
}
__device__ __forceinline__ float tanh_fast(float x) {
    float r; asm("tanh.approx.f32 %0, %1;" : "=f"(r) : "f"(x)); return r;
}

// ---------------- K1: q,k + housekeeping --------------------------------------
__global__ void qk_kernel(const float* __restrict__ x,
                          const float* __restrict__ Wq, const float* __restrict__ bq,
                          const float* __restrict__ Wk, const float* __restrict__ bk,
                          const float* __restrict__ Wv) {
    __shared__ float xm[C_];
    int b = blockIdx.x; int n = b >> 9; int t = b & 511;
    int tid = threadIdx.x;
    int c = tid;

    if (b < 128) {
        g_vsum[b * 128 + tid] = 0.f;
    } else if (b == 128) {
        g_chsum[tid] = 0.f; g_chsq[tid] = 0.f;
    } else if (b >= 256 && b < 384) {
        int i = (b - 256) * 128 + tid;
        int o = i >> 7, cc = i & 127;
        g_wvt[cc * O_ + o] = Wv[i];
    }

    const float* xp = x + ((n * C_ + c) * T_ + t) * V_;
    float s = 0.f;
#pragma unroll
    for (int v = 0; v < V_; v++) s += xp[v];
    xm[c] = s * (1.0f / 25.0f);
    __syncthreads();
    if (tid < 32) {
        int h = tid & 15;
        bool isQ = tid < 16;
        const float* W = isQ ? Wq : Wk;
        float acc = isQ ? bq[h] : bk[h];
#pragma unroll 8
        for (int cc = 0; cc < C_; cc++) acc += W[h * C_ + cc] * xm[cc];
        float* dst = isQ ? g_q : g_k;
        dst[(n * T_ + t) * H_ + h] = acc;
    }
}

// ---------------- K2: v projection --------------------------------------------
__global__ void v_kernel(const float* __restrict__ x, const float* __restrict__ bv) {
    __shared__ float xs[C_][28];
    int b = blockIdx.x; int n = b >> 9; int t = b & 511;
    int o = threadIdx.x;
    {
        const float* xp = x + ((n * C_ + o) * T_ + t) * V_;
#pragma unroll
        for (int v = 0; v < V_; v++) xs[o][v] = xp[v];
        xs[o][25] = 0.f; xs[o][26] = 0.f; xs[o][27] = 0.f;
    }
    __syncthreads();
    ull acc[13];
    ull binit = dup2(bv[o]);
#pragma unroll
    for (int j = 0; j < 13; j++) acc[j] = binit;
    for (int c = 0; c < C_; c++) {
        ull wd = dup2(g_wvt[c * O_ + o]);
        const ulonglong2* xr = (const ulonglong2*)xs[c];
#pragma unroll
        for (int j = 0; j < 6; j++) {
            ulonglong2 p = xr[j];
            acc[2 * j]     = ffma2(wd, p.x, acc[2 * j]);
            acc[2 * j + 1] = ffma2(wd, p.y, acc[2 * j + 1]);
        }
        acc[12] = ffma2(wd, *((const ull*)xs[c] + 12), acc[12]);
    }
    float* row = g_v + (((size_t)(n * T_ + t)) * O_ + o) * 32;
#pragma unroll
    for (int j = 0; j < 12; j++) {
        float2 u = unpack2(acc[j]);
        row[2 * j] = u.x; row[2 * j + 1] = u.y;
    }
    { float2 u = unpack2(acc[12]); row[24] = u.x; }
#pragma unroll
    for (int p = 25; p < 32; p++) row[p] = 0.f;
}

// ---------------- K3: vsum ------------------------------------------------------
__global__ void vsum_kernel() {
    __shared__ float red[8][33];
    int bx = blockIdx.x;
    int n = bx >> 8, o = (bx >> 1) & 127, half = bx & 1;
    int tid = threadIdx.x;
    int tsub = tid >> 5, comp = tid & 31;
    int t0 = half * 256 + tsub * 32;
    const float* base = g_v + (((size_t)(n * T_ + t0)) * O_ + o) * 32 + comp;
    float a0 = 0.f, a1 = 0.f, a2 = 0.f, a3 = 0.f;
#pragma unroll
    for (int u = 0; u < 32; u += 4) {
        a0 += base[(size_t)(u + 0) * O_ * 32];
        a1 += base[(size_t)(u + 1) * O_ * 32];
        a2 += base[(size_t)(u + 2) * O_ * 32];
        a3 += base[(size_t)(u + 3) * O_ * 32];
    }
    red[tsub][comp] = (a0 + a1) + (a2 + a3);
    __syncthreads();
    if (tsub == 0) {
        float s = 0.f;
#pragma unroll
        for (int r = 0; r < 8; r++) s += red[r][comp];
        atomicAdd(&g_vsum[(n * O_ + o) * 32 + comp], s);
    }
}

// ---------------- K4: fused attention — single barrier/chunk, no spills ----------
// 256 threads, tile (n, o16, g16). grid 1024, 2 blocks/SM, 128 regs.
#define TCH 8
#define NCHUNK (T_ / TCH)            // 64
#define ROWP 132
#define SM_SS 8192
#define SM_AS (SM_SS + 2 * 16 * ROWP)   // 12416
#define SM_TOT (SM_AS + 2 * 16 * ROWP)  // 16640 floats = 66560 B
#define SBUF (16 * ROWP)
#define ABUF (16 * ROWP)

// tanh stage
__device__ __forceinline__ void a_stage(const float* __restrict__ k_s, float* __restrict__ Sb,
                                        float qv, int gA, int hA, int cc) {
    const float* kp = k_s + cc * TCH * 16 + hA;
    float* so = Sb + gA * ROWP + hA;
#pragma unroll
    for (int tt = 0; tt < TCH; tt++) so[tt * 16] = tanh_fast(qv - kp[tt * 16]);
}

// B stage: A[o][tt*16 + g0..7] = Wr[o,:] . S[g][tt][:]
__device__ __forceinline__ void b_stage(const float* __restrict__ Sb, float* __restrict__ Ab,
                                        const ull* __restrict__ w, int oB, int ttB, int ghB) {
    float outv[8];
    const float* srow = Sb + ttB * 16;
#pragma unroll
    for (int i = 0; i < 8; i++) {
        int g = ghB * 8 + i;
        const ulonglong2* sp = (const ulonglong2*)(srow + g * ROWP);
        ulonglong2 sa = sp[0], sb2 = sp[1];
        ull a0 = fmul2(w[0], sa.x);  a0 = ffma2(w[1], sa.y, a0);
        a0 = ffma2(w[2], sb2.x, a0); a0 = ffma2(w[3], sb2.y, a0);
        ulonglong2 sc = sp[2], sd = sp[3];
        ull a1 = fmul2(w[4], sc.x);  a1 = ffma2(w[5], sc.y, a1);
        a1 = ffma2(w[6], sd.x, a1);  a1 = ffma2(w[7], sd.y, a1);
        float2 u = unpack2(fadd2(a0, a1));
        outv[i] = u.x + u.y;
    }
    float4* dst = (float4*)(Ab + oB * ROWP + ttB * 16 + ghB * 8);
    dst[0] = make_float4(outv[0], outv[1], outv[2], outv[3]);
    dst[1] = make_float4(outv[4], outv[5], outv[6], outv[7]);
}

// C stage: all 16 g per tt
__device__ __forceinline__ void c_full(const float* __restrict__ Ab, int oC,
                                       const ull* __restrict__ vc,
                                       ull* __restrict__ acc0, ull* __restrict__ acc1) {
    const float* arow = Ab + oC * ROWP;
#pragma unroll
    for (int tt = 0; tt < TCH; tt++) {
        const ulonglong2* ap = (const ulonglong2*)(arow + tt * 16);
        ulonglong2 aA = ap[0], aB = ap[1], aC = ap[2], aD = ap[3];
        float2 vv = unpack2(vc[tt]);
        ull d0 = dup2(vv.x), d1 = dup2(vv.y);
        acc0[0] = ffma2(aA.x, d0, acc0[0]);
        acc0[1] = ffma2(aA.y, d0, acc0[1]);
        acc0[2] = ffma2(aB.x, d0, acc0[2]);
        acc0[3] = ffma2(aB.y, d0, acc0[3]);
        acc0[4] = ffma2(aC.x, d0, acc0[4]);
        acc0[5] = ffma2(aC.y, d0, acc0[5]);
        acc0[6] = ffma2(aD.x, d0, acc0[6]);
        acc0[7] = ffma2(aD.y, d0, acc0[7]);
        acc1[0] = ffma2(aA.x, d1, acc1[0]);
        acc1[1] = ffma2(aA.y, d1, acc1[1]);
        acc1[2] = ffma2(aB.x, d1, acc1[2]);
        acc1[3] = ffma2(aB.y, d1, acc1[3]);
        acc1[4] = ffma2(aC.x, d1, acc1[4]);
        acc1[5] = ffma2(aC.y, d1, acc1[5]);
        acc1[6] = ffma2(aD.x, d1, acc1[6]);
        acc1[7] = ffma2(aD.y, d1, acc1[7]);
    }
}

__global__ void __launch_bounds__(256, 2)
attn_kernel(const float* __restrict__ Wr, const float* __restrict__ br) {
    extern __shared__ float sm[];
    float* k_s = sm;
    float* S_s = sm + SM_SS;
    float* A_s = sm + SM_AS;

    int bx = blockIdx.x;
    int gt = bx & 31, ot = (bx >> 5) & 7, n = bx >> 8;
    int o_base = ot * 16, g_base = gt * 16;
    int tid = threadIdx.x;

    // roles
    int hA = tid & 15, gA = tid >> 4;                        // tanh stage
    int oB = tid & 15, ttB = (tid >> 4) & 7, ghB = tid >> 7; // B stage
    int oC = tid / 13, jC = tid - oC * 13;                   // C stage (tid<208)
    bool actC = tid < 208;

    // load k slice
    {
        const float4* kg = (const float4*)(g_k + n * T_ * H_);
        float4* k4 = (float4*)k_s;
#pragma unroll
        for (int i = 0; i < 8; i++) k4[tid + i * 256] = kg[tid + i * 256];
    }
    float qv = g_q[(n * T_ + g_base + gA) * H_ + hA];

    ull w[8];
    {
        const ull* wp = (const ull*)(Wr + (o_base + oB) * H_);
#pragma unroll
        for (int j = 0; j < 8; j++) w[j] = wp[j];
    }

    ull acc0[8], acc1[8];
    ull vcur[8], vnext[8];
    const float* vbase = g_v + (((size_t)n * T_) * O_ + o_base + oC) * 32 + 2 * jC;
    if (actC) {
        float brv = br[o_base + oC];
        const float* vs = g_vsum + (n * O_ + o_base + oC) * 32 + 2 * jC;
        ull i0 = dup2(brv * vs[0]);
        ull i1 = dup2(brv * vs[1]);
#pragma unroll
        for (int p = 0; p < 8; p++) { acc0[p] = i0; acc1[p] = i1; }
#pragma unroll
        for (int tt = 0; tt < TCH; tt++)
            vcur[tt] = *(const ull*)(vbase + (size_t)tt * O_ * 32);
    }
    __syncthreads();   // k_s visible

    // prologue: S(0) -> buf0
    a_stage(k_s, S_s, qv, gA, hA, 0);
    __syncthreads();
    // prologue: S(1) -> buf1, B(0) -> A buf0
    a_stage(k_s, S_s + SBUF, qv, gA, hA, 1);
    b_stage(S_s, A_s, w, oB, ttB, ghB);
    __syncthreads();

    // main loop: ONE barrier per chunk
    for (int c = 0; c < NCHUNK; c++) {
        int ab = c & 1;
        // prefetch v(c+1) first (longest latency)
        if (actC && c < NCHUNK - 1) {
            const float* vb2 = vbase + (size_t)(c + 1) * TCH * O_ * 32;
#pragma unroll
            for (int tt = 0; tt < TCH; tt++)
                vnext[tt] = *(const ull*)(vb2 + (size_t)tt * O_ * 32);
        }
        if (c < NCHUNK - 2)
            a_stage(k_s, S_s + ab * SBUF, qv, gA, hA, c + 2);        // S(c+2) -> buf c&1
        if (c < NCHUNK - 1)
            b_stage(S_s + (ab ^ 1) * SBUF, A_s + (ab ^ 1) * ABUF, w, oB, ttB, ghB); // A(c+1)
        if (actC) {
            c_full(A_s + ab * ABUF, oC, vcur, acc0, acc1);           // consume A(c)
#pragma unroll
            for (int tt = 0; tt < TCH; tt++) vcur[tt] = vnext[tt];
        }
        __syncthreads();
    }

    // ---- epilogue: y writes + BN partial stats ----
    float sum = 0.f, sq = 0.f;
    if (actC) {
        int o0 = o_base + oC;
        float* ybase = g_y + (((size_t)(n * O_ + o0)) * T_ + g_base) * 26 + 2 * jC;
#pragma unroll
        for (int p = 0; p < 8; p++) {
            float2 u0 = unpack2(acc0[p]);
            float2 u1 = unpack2(acc1[p]);
            *(ull*)(ybase + (2 * p) * 26)     = pack2(u0.x, u1.x);
            *(ull*)(ybase + (2 * p + 1) * 26) = pack2(u0.y, u1.y);
            sum += u0.x + u0.y + u1.x + u1.y;
            sq  += u0.x * u0.x + u0.y * u0.y + u1.x * u1.x + u1.y * u1.y;
        }
    }
    __syncthreads();
    float* red = sm;
    if (tid < 32) red[tid] = 0.f;
    __syncthreads();
    if (actC) {
        atomicAdd(&red[oC], sum);
        atomicAdd(&red[16 + oC], sq);
    }
    __syncthreads();
    if (tid < 16)       atomicAdd(&g_chsum[o_base + tid], red[tid]);
    else if (tid < 32)  atomicAdd(&g_chsq[o_base + tid - 16], red[tid]);
}

// ---------------- K5: BN + residual + ReLU ----------------------------------------
__global__ void bn_kernel(const float* __restrict__ x,
                          const float* __restrict__ gamma, const float* __restrict__ beta,
                          float* __restrict__ out) {
    int bx = blockIdx.x;
    int n = bx >> 7, o = bx & 127;
    int tid = threadIdx.x;
    float mu  = g_chsum[o] * (1.0f / YCNT);
    float var = g_chsq[o] * (1.0f / YCNT) - mu * mu;
    float r = rsqrtf(var + EPS_);
    float gam = gamma[o] * r;
    float bet = beta[o] - mu * gam;
    const float* xb = x + (((size_t)(n * C_ + o)) * T_) * V_;
    const float* yb = g_y + ((size_t)(n * O_ + o)) * T_ * 26;
    float* ob = out + (((size_t)(n * O_ + o)) * T_) * V_;
#pragma unroll
    for (int i = 0; i < 25; i++) {
        int e = tid + i * 512;
        int t = (int)(((unsigned)e * 5243u) >> 17);
        float yv = yb[e + t];
        float val = yv * gam + bet + xb[e];
        ob[e] = fmaxf(val, 0.f);
    }
}

// ---------------- launcher ----------------------------------------------------------
extern "C" void kernel_launch(void* const* d_in, const int* in_sizes, int n_in,
                              void* d_out, int out_size) {
    const float* x     = (const float*)d_in[0];
    const float* Wq    = (const float*)d_in[1];
    const float* bq    = (const float*)d_in[2];
    const float* Wk    = (const float*)d_in[3];
    const float* bk    = (const float*)d_in[4];
    const float* Wv    = (const float*)d_in[5];
    const float* bv    = (const float*)d_in[6];
    const float* Wr    = (const float*)d_in[7];
    const float* br    = (const float*)d_in[8];
    const float* gamma = (const float*)d_in[9];
    const float* beta  = (const float*)d_in[10];
    float* out = (float*)d_out;

    const int smem_bytes = SM_TOT * 4;   // 66560
    cudaFuncSetAttribute(attn_kernel, cudaFuncAttributeMaxDynamicSharedMemorySize, smem_bytes);

    qk_kernel<<<N_ * T_, 128>>>(x, Wq, bq, Wk, bk, Wv);   // 1 (+housekeeping)
    v_kernel<<<N_ * T_, 128>>>(x, bv);                     // 2
    vsum_kernel<<<1024, 256>>>();                          // 3
    attn_kernel<<<1024, 256, smem_bytes>>>(Wr, br);        // 4  <- profiled
    bn_kernel<<<512, 512>>>(x, gamma, beta, out);          // 5
}

// round 9
// speedup vs baseline: 1.3503x; 1.0531x over previous
#include <cuda_runtime.h>

#define N_ 4
#define C_ 128
#define T_ 512
#define V_ 25
#define H_ 16
#define O_ 128
#define EPS_ 1e-5f
#define YCNT 51200.0f   // N*T*V

typedef unsigned long long ull;

// ---------------- scratch ----------------------------------------------------
__device__ float g_q[N_ * T_ * H_];          // [n][t][h]
__device__ float g_k[N_ * T_ * H_];          // [n][t][h]
__device__ float g_wvt[C_ * O_];             // [c][o]
__device__ float g_v[N_ * T_ * O_ * 32];     // [n][t][o][32] (25 data + zeros)
__device__ float g_vsum[N_ * O_ * 32];       // [n][o][32]
__device__ float g_y[(size_t)N_ * O_ * T_ * 26]; // [n][o][g][26]
__device__ float g_chsum[O_];
__device__ float g_chsq[O_];

// ---------------- helpers -----------------------------------------------------
__device__ __forceinline__ ull ffma2(ull a, ull b, ull c) {
    ull d; asm("fma.rn.f32x2 %0, %1, %2, %3;" : "=l"(d) : "l"(a), "l"(b), "l"(c)); return d;
}
__device__ __forceinline__ ull fmul2(ull a, ull b) {
    ull d; asm("mul.rn.f32x2 %0, %1, %2;" : "=l"(d) : "l"(a), "l"(b)); return d;
}
__device__ __forceinline__ ull fadd2(ull a, ull b) {
    ull d; asm("add.rn.f32x2 %0, %1, %2;" : "=l"(d) : "l"(a), "l"(b)); return d;
}
__device__ __forceinline__ ull dup2(float x) {
    ull d; asm("mov.b64 %0, {%1, %1};" : "=l"(d) : "f"(x)); return d;
}
__device__ __forceinline__ float2 unpack2(ull a) {
    float2 r; asm("mov.b64 {%0, %1}, %2;" : "=f"(r.x), "=f"(r.y) : "l"(a)); return r;
}
__device__ __forceinline__ float tanh_fast(float x) {
    float r; asm("tanh.approx.f32 %0, %1;" : "=f"(r) : "f"(x)); return r;
}

// ---------------- K1: q,k + housekeeping --------------------------------------
__global__ void qk_kernel(const float* __restrict__ x,
                          const float* __restrict__ Wq, const float* __restrict__ bq,
                          const float* __restrict__ Wk, const float* __restrict__ bk,
                          const float* __restrict__ Wv) {
    __shared__ float xm[C_];
    int b = blockIdx.x; int n = b >> 9; int t = b & 511;
    int tid = threadIdx.x;
    int c = tid;

    if (b < 128) {
        g_vsum[b * 128 + tid] = 0.f;
    } else if (b == 128) {
        g_chsum[tid] = 0.f; g_chsq[tid] = 0.f;
    } else if (b >= 256 && b < 384) {
        int i = (b - 256) * 128 + tid;
        int o = i >> 7, cc = i & 127;
        g_wvt[cc * O_ + o] = Wv[i];
    }

    const float* xp = x + ((n * C_ + c) * T_ + t) * V_;
    float s = 0.f;
#pragma unroll
    for (int v = 0; v < V_; v++) s += xp[v];
    xm[c] = s * (1.0f / 25.0f);
    __syncthreads();
    if (tid < 32) {
        int h = tid & 15;
        bool isQ = tid < 16;
        const float* W = isQ ? Wq : Wk;
        float acc = isQ ? bq[h] : bk[h];
#pragma unroll 8
        for (int cc = 0; cc < C_; cc++) acc += W[h * C_ + cc] * xm[cc];
        float* dst = isQ ? g_q : g_k;
        dst[(n * T_ + t) * H_ + h] = acc;
    }
}

// ---------------- K2: v projection --------------------------------------------
__global__ void v_kernel(const float* __restrict__ x, const float* __restrict__ bv) {
    __shared__ float xs[C_][28];
    int b = blockIdx.x; int n = b >> 9; int t = b & 511;
    int o = threadIdx.x;
    {
        const float* xp = x + ((n * C_ + o) * T_ + t) * V_;
#pragma unroll
        for (int v = 0; v < V_; v++) xs[o][v] = xp[v];
        xs[o][25] = 0.f; xs[o][26] = 0.f; xs[o][27] = 0.f;
    }
    __syncthreads();
    ull acc[13];
    ull binit = dup2(bv[o]);
#pragma unroll
    for (int j = 0; j < 13; j++) acc[j] = binit;
    for (int c = 0; c < C_; c++) {
        ull wd = dup2(g_wvt[c * O_ + o]);
        const ulonglong2* xr = (const ulonglong2*)xs[c];
#pragma unroll
        for (int j = 0; j < 6; j++) {
            ulonglong2 p = xr[j];
            acc[2 * j]     = ffma2(wd, p.x, acc[2 * j]);
            acc[2 * j + 1] = ffma2(wd, p.y, acc[2 * j + 1]);
        }
        acc[12] = ffma2(wd, *((const ull*)xs[c] + 12), acc[12]);
    }
    float* row = g_v + (((size_t)(n * T_ + t)) * O_ + o) * 32;
#pragma unroll
    for (int j = 0; j < 12; j++) {
        float2 u = unpack2(acc[j]);
        row[2 * j] = u.x; row[2 * j + 1] = u.y;
    }
    { float2 u = unpack2(acc[12]); row[24] = u.x; }
#pragma unroll
    for (int p = 25; p < 32; p++) row[p] = 0.f;
}

// ---------------- K3: vsum ------------------------------------------------------
__global__ void vsum_kernel() {
    __shared__ float red[8][33];
    int bx = blockIdx.x;
    int n = bx >> 8, o = (bx >> 1) & 127, half = bx & 1;
    int tid = threadIdx.x;
    int tsub = tid >> 5, comp = tid & 31;
    int t0 = half * 256 + tsub * 32;
    const float* base = g_v + (((size_t)(n * T_ + t0)) * O_ + o) * 32 + comp;
    float a0 = 0.f, a1 = 0.f, a2 = 0.f, a3 = 0.f;
#pragma unroll
    for (int u = 0; u < 32; u += 4) {
        a0 += base[(size_t)(u + 0) * O_ * 32];
        a1 += base[(size_t)(u + 1) * O_ * 32];
        a2 += base[(size_t)(u + 2) * O_ * 32];
        a3 += base[(size_t)(u + 3) * O_ * 32];
    }
    red[tsub][comp] = (a0 + a1) + (a2 + a3);
    __syncthreads();
    if (tsub == 0) {
        float s = 0.f;
#pragma unroll
        for (int r = 0; r < 8; r++) s += red[r][comp];
        atomicAdd(&g_vsum[(n * O_ + o) * 32 + comp], s);
    }
}

// ---------------- K4: fused attention — 512 thr, 64 regs, 32 warps/SM -----------
#define TCH 8
#define NCHUNK (T_ / TCH)            // 64
#define ROWP 132
#define SM_SS 8192
#define SM_AS (SM_SS + 2 * 16 * ROWP)   // 12416
#define SM_TOT (SM_AS + 2 * 16 * ROWP)  // 16640 floats = 66560 B
#define SBUF (16 * ROWP)
#define ABUF (16 * ROWP)

// tanh stage: 4 tt per thread
__device__ __forceinline__ void a_stage4(const float* __restrict__ k_s, float* __restrict__ Sb,
                                         float qv, int gA, int hA, int tth, int cc) {
    const float* kp = k_s + cc * TCH * 16 + tth * 64 + hA;
    float* so = Sb + gA * ROWP + tth * 64 + hA;
#pragma unroll
    for (int tt = 0; tt < 4; tt++) so[tt * 16] = tanh_fast(qv - kp[tt * 16]);
}

// B stage: 4 g per thread: A[o][tt*16 + gq*4 .. +3] = Wr[o,:] . S[g][tt][:]
__device__ __forceinline__ void b_stage4(const float* __restrict__ Sb, float* __restrict__ Ab,
                                         const ull* __restrict__ w, int oB, int ttB, int gq) {
    float outv[4];
    const float* srow = Sb + ttB * 16;
#pragma unroll
    for (int i = 0; i < 4; i++) {
        int g = gq * 4 + i;
        const ulonglong2* sp = (const ulonglong2*)(srow + g * ROWP);
        ulonglong2 s0 = sp[0], s1 = sp[1];
        ull a0 = fmul2(w[0], s0.x);  a0 = ffma2(w[1], s0.y, a0);
        a0 = ffma2(w[2], s1.x, a0);  a0 = ffma2(w[3], s1.y, a0);
        ulonglong2 s2 = sp[2], s3 = sp[3];
        ull a1 = fmul2(w[4], s2.x);  a1 = ffma2(w[5], s2.y, a1);
        a1 = ffma2(w[6], s3.x, a1);  a1 = ffma2(w[7], s3.y, a1);
        float2 u = unpack2(fadd2(a0, a1));
        outv[i] = u.x + u.y;
    }
    *(float4*)(Ab + oB * ROWP + ttB * 16 + gq * 4) =
        make_float4(outv[0], outv[1], outv[2], outv[3]);
}

// C stage: scalar v, acc = 8 f32x2 pairs over g
__device__ __forceinline__ void c_scalar(const float* __restrict__ Ab, int oC,
                                         const float* __restrict__ vc, ull* __restrict__ acc) {
    const float* arow = Ab + oC * ROWP;
#pragma unroll
    for (int tt = 0; tt < TCH; tt++) {
        const ulonglong2* ap = (const ulonglong2*)(arow + tt * 16);
        ull d = dup2(vc[tt]);
        ulonglong2 p0 = ap[0], p1 = ap[1];
        acc[0] = ffma2(p0.x, d, acc[0]);
        acc[1] = ffma2(p0.y, d, acc[1]);
        acc[2] = ffma2(p1.x, d, acc[2]);
        acc[3] = ffma2(p1.y, d, acc[3]);
        ulonglong2 p2 = ap[2], p3 = ap[3];
        acc[4] = ffma2(p2.x, d, acc[4]);
        acc[5] = ffma2(p2.y, d, acc[5]);
        acc[6] = ffma2(p3.x, d, acc[6]);
        acc[7] = ffma2(p3.y, d, acc[7]);
    }
}

__global__ void __launch_bounds__(512, 2)
attn_kernel(const float* __restrict__ Wr, const float* __restrict__ br) {
    extern __shared__ float sm[];
    float* k_s = sm;
    float* S_s = sm + SM_SS;
    float* A_s = sm + SM_AS;

    int bx = blockIdx.x;
    int gt = bx & 31, ot = (bx >> 5) & 7, n = bx >> 8;
    int o_base = ot * 16, g_base = gt * 16;
    int tid = threadIdx.x;

    // roles
    int hA = tid & 15, gA = (tid >> 4) & 15, tth = tid >> 8;   // tanh: 4 tt each
    int oB = tid & 15, ttB = (tid >> 4) & 7, gq = tid >> 7;    // B: 4 g each (gq 0..3)
    int oC = tid / 26, vC = tid - oC * 26;                     // C: scalar v (tid<416)
    bool actC = tid < 416;

    // load k slice (2048 float4)
    {
        const float4* kg = (const float4*)(g_k + n * T_ * H_);
        float4* k4 = (float4*)k_s;
#pragma unroll
        for (int i = 0; i < 4; i++) k4[tid + i * 512] = kg[tid + i * 512];
    }
    float qv = g_q[(n * T_ + g_base + gA) * H_ + hA];

    ull w[8];
    {
        const ull* wp = (const ull*)(Wr + (o_base + oB) * H_);
#pragma unroll
        for (int j = 0; j < 8; j++) w[j] = wp[j];
    }

    ull acc[8];
    float vcur[8];
    const float* vbase = actC
        ? g_v + (((size_t)n * T_) * O_ + o_base + oC) * 32 + vC
        : g_v;
    if (actC) {
        float brv = br[o_base + oC];
        float vs = g_vsum[(n * O_ + o_base + oC) * 32 + vC];
        ull i0 = dup2(brv * vs);
#pragma unroll
        for (int p = 0; p < 8; p++) acc[p] = i0;
#pragma unroll
        for (int tt = 0; tt < TCH; tt++)
            vcur[tt] = vbase[(size_t)tt * O_ * 32];
    }
    __syncthreads();   // k_s visible

    // prologue
    a_stage4(k_s, S_s, qv, gA, hA, tth, 0);           // S(0) -> buf0
    __syncthreads();
    a_stage4(k_s, S_s + SBUF, qv, gA, hA, tth, 1);    // S(1) -> buf1
    b_stage4(S_s, A_s, w, oB, ttB, gq);               // A(0) -> buf0
    __syncthreads();

    // main loop: ONE barrier per chunk
    for (int c = 0; c < NCHUNK; c++) {
        int ab = c & 1;
        if (c < NCHUNK - 2)
            a_stage4(k_s, S_s + ab * SBUF, qv, gA, hA, tth, c + 2);
        if (c < NCHUNK - 1)
            b_stage4(S_s + (ab ^ 1) * SBUF, A_s + (ab ^ 1) * ABUF, w, oB, ttB, gq);
        if (actC) {
            c_scalar(A_s + ab * ABUF, oC, vcur, acc);
            if (c < NCHUNK - 1) {
                const float* vb2 = vbase + (size_t)(c + 1) * TCH * O_ * 32;
#pragma unroll
                for (int tt = 0; tt < TCH; tt++)
                    vcur[tt] = vb2[(size_t)tt * O_ * 32];
            }
        }
        __syncthreads();
    }

    // ---- epilogue: y writes + BN partial stats ----
    float sum = 0.f, sq = 0.f;
    if (actC) {
        int o0 = o_base + oC;
        float* ybase = g_y + (((size_t)(n * O_ + o0)) * T_ + g_base) * 26 + vC;
#pragma unroll
        for (int p = 0; p < 8; p++) {
            float2 u = unpack2(acc[p]);
            ybase[(2 * p) * 26]     = u.x;
            ybase[(2 * p + 1) * 26] = u.y;
            sum += u.x + u.y;
            sq  += u.x * u.x + u.y * u.y;
        }
    }
    __syncthreads();
    float* red = sm;
    if (tid < 32) red[tid] = 0.f;
    __syncthreads();
    if (actC) {
        atomicAdd(&red[oC], sum);
        atomicAdd(&red[16 + oC], sq);
    }
    __syncthreads();
    if (tid < 16)       atomicAdd(&g_chsum[o_base + tid], red[tid]);
    else if (tid < 32)  atomicAdd(&g_chsq[o_base + tid - 16], red[tid]);
}

// ---------------- K5: BN + residual + ReLU ----------------------------------------
__global__ void bn_kernel(const float* __restrict__ x,
                          const float* __restrict__ gamma, const float* __restrict__ beta,
                          float* __restrict__ out) {
    int bx = blockIdx.x;
    int n = bx >> 7, o = bx & 127;
    int tid = threadIdx.x;
    float mu  = g_chsum[o] * (1.0f / YCNT);
    float var = g_chsq[o] * (1.0f / YCNT) - mu * mu;
    float r = rsqrtf(var + EPS_);
    float gam = gamma[o] * r;
    float bet = beta[o] - mu * gam;
    const float* xb = x + (((size_t)(n * C_ + o)) * T_) * V_;
    const float* yb = g_y + ((size_t)(n * O_ + o)) * T_ * 26;
    float* ob = out + (((size_t)(n * O_ + o)) * T_) * V_;
#pragma unroll
    for (int i = 0; i < 25; i++) {
        int e = tid + i * 512;
        int t = (int)(((unsigned)e * 5243u) >> 17);
        float yv = yb[e + t];
        float val = yv * gam + bet + xb[e];
        ob[e] = fmaxf(val, 0.f);
    }
}

// ---------------- launcher ----------------------------------------------------------
extern "C" void kernel_launch(void* const* d_in, const int* in_sizes, int n_in,
                              void* d_out, int out_size) {
    const float* x     = (const float*)d_in[0];
    const float* Wq    = (const float*)d_in[1];
    const float* bq    = (const float*)d_in[2];
    const float* Wk    = (const float*)d_in[3];
    const float* bk    = (const float*)d_in[4];
    const float* Wv    = (const float*)d_in[5];
    const float* bv    = (const float*)d_in[6];
    const float* Wr    = (const float*)d_in[7];
    const float* br    = (const float*)d_in[8];
    const float* gamma = (const float*)d_in[9];
    const float* beta  = (const float*)d_in[10];
    float* out = (float*)d_out;

    const int smem_bytes = SM_TOT * 4;   // 66560
    cudaFuncSetAttribute(attn_kernel, cudaFuncAttributeMaxDynamicSharedMemorySize, smem_bytes);

    qk_kernel<<<N_ * T_, 128>>>(x, Wq, bq, Wk, bk, Wv);   // 1 (+housekeeping)
    v_kernel<<<N_ * T_, 128>>>(x, bv);                     // 2
    vsum_kernel<<<1024, 256>>>();                          // 3
    attn_kernel<<<1024, 512, smem_bytes>>>(Wr, br);        // 4  <- profiled
    bn_kernel<<<512, 512>>>(x, gamma, beta, out);          // 5
}